// round 14
// baseline (speedup 1.0000x reference)
#include <cuda_runtime.h>
#include <cuda_fp16.h>
#include <math.h>
#include <stdint.h>

#define SEQ   2048
#define DIM   4096
#define NH    32
#define NKV   8
#define HD    128
#define KVDIM (NKV * HD)   // 1024
#define NQKV  (DIM + 2 * KVDIM)   // 6144

// Scratch (device globals: allocation-free rule)
__device__ float  g_qkv[SEQ * NQKV];          // fused QKV projection output (fp32)
__device__ __half g_qh[SEQ * DIM];            // roped+scaled Q (half)
__device__ __half g_kh[SEQ * KVDIM];          // roped K (half)
__device__ __half g_vth[KVDIM * SEQ];         // V transposed [kvdim][seq] (half)
__device__ __half g_yh[SEQ * DIM];            // attention output (half)
__device__ __half g_xh[SEQ * DIM];
__device__ __half g_wqkvh[NQKV * DIM];        // fused [wq; wk; wv] (half)
__device__ __half g_woh[DIM * DIM];

// ---------------------------------------------------------------------------
// Helpers
// ---------------------------------------------------------------------------
__device__ __forceinline__ unsigned h2u(__half2 h) { return *(unsigned*)&h; }

__device__ __forceinline__ void cp16(void* smem_dst, const void* gsrc) {
    unsigned d = (unsigned)__cvta_generic_to_shared(smem_dst);
    asm volatile("cp.async.cg.shared.global [%0], [%1], 16;" :: "r"(d), "l"(gsrc));
}
__device__ __forceinline__ void mma_f16(float c[4], const unsigned a[4], const unsigned b[2]) {
    asm volatile(
        "mma.sync.aligned.m16n8k16.row.col.f32.f16.f16.f32 "
        "{%0,%1,%2,%3}, {%4,%5,%6,%7}, {%8,%9}, {%0,%1,%2,%3};"
        : "+f"(c[0]), "+f"(c[1]), "+f"(c[2]), "+f"(c[3])
        : "r"(a[0]), "r"(a[1]), "r"(a[2]), "r"(a[3]), "r"(b[0]), "r"(b[1]));
}

// fp32 -> fp16 conversion prepass
__global__ void cvt_h_kernel(const float* __restrict__ in, __half* __restrict__ out,
                             int n4) {
    int i = blockIdx.x * blockDim.x + threadIdx.x;
    if (i >= n4) return;
    float4 v = ((const float4*)in)[i];
    ((uint2*)out)[i] = make_uint2(h2u(__floats2half2_rn(v.x, v.y)),
                                  h2u(__floats2half2_rn(v.z, v.w)));
}

// ---------------------------------------------------------------------------
// FP16 GEMM (NT): C[M,N] = A[M,K] * B[N,K]^T, fp16 in / fp32 out.
// 128x128 tile, BK=32, 256 thr, 8 warps x (64x32), cp.async 3-stage pipeline.
// ---------------------------------------------------------------------------
#define GSH 56   // smem row stride in halves (112B, conflict-free, 16B-aligned)
#define NSTG 3
#define GEMM_SMEM (2 * NSTG * 128 * GSH * 2)   // 86016 B

__global__ __launch_bounds__(256, 2)
void gemm_f16_kernel(const __half* __restrict__ A, const __half* __restrict__ B,
                     float* __restrict__ C, int M, int N, int K) {
    extern __shared__ __half hsm[];
    __half* As = hsm;                      // [NSTG][128*GSH]
    __half* Bs = hsm + NSTG * 128 * GSH;

    const int tid  = threadIdx.x;
    const int lane = tid & 31;
    const int wid  = tid >> 5;
    const int grp  = lane >> 2;
    const int tig  = lane & 3;

    const int bm = blockIdx.y * 128;
    const int bn = blockIdx.x * 128;
    const int wm = (wid & 1) * 64;
    const int wn = (wid >> 1) * 32;

    float acc[4][4][4];
#pragma unroll
    for (int i = 0; i < 4; i++)
#pragma unroll
        for (int j = 0; j < 4; j++)
#pragma unroll
            for (int t = 0; t < 4; t++) acc[i][j][t] = 0.0f;

    const int nk = K / 32;

    auto load_stage = [&](int t, int buf) {
        const int koff = t * 32;
        __half* Ad = As + buf * 128 * GSH;
        __half* Bd = Bs + buf * 128 * GSH;
#pragma unroll
        for (int u = 0; u < 2; u++) {
            int id  = tid + u * 256;
            int row = id >> 2;
            int o8  = (id & 3) * 8;
            cp16(Ad + row * GSH + o8, A + (size_t)(bm + row) * K + koff + o8);
            cp16(Bd + row * GSH + o8, B + (size_t)(bn + row) * K + koff + o8);
        }
    };

    // prologue: stages 0,1
    load_stage(0, 0);
    asm volatile("cp.async.commit_group;");
    load_stage(1, 1);
    asm volatile("cp.async.commit_group;");

    int buf = 0;   // buffer of chunk t
    for (int t = 0; t < nk; t++) {
        if (t + 2 < nk) {
            int nb = buf + 2; if (nb >= NSTG) nb -= NSTG;
            load_stage(t + 2, nb);
            asm volatile("cp.async.commit_group;");
        }
        // groups allowed pending after this point: min(2, nk-1-t)
        int rem = nk - 1 - t;
        if (rem >= 2)      asm volatile("cp.async.wait_group 2;");
        else if (rem == 1) asm volatile("cp.async.wait_group 1;");
        else               asm volatile("cp.async.wait_group 0;");
        __syncthreads();

        const __half* Ab = As + buf * 128 * GSH;
        const __half* Bb = Bs + buf * 128 * GSH;
#pragma unroll
        for (int kk = 0; kk < 2; kk++) {      // two k16 steps per BK=32
            const int ko = kk * 16;
            unsigned af[4][4], bf[4][2];
#pragma unroll
            for (int i = 0; i < 4; i++) {
                const __half* base = Ab + (wm + i * 16 + grp) * GSH + ko + 2 * tig;
                af[i][0] = *(const unsigned*)(base);
                af[i][1] = *(const unsigned*)(base + 8 * GSH);
                af[i][2] = *(const unsigned*)(base + 8);
                af[i][3] = *(const unsigned*)(base + 8 * GSH + 8);
            }
#pragma unroll
            for (int j = 0; j < 4; j++) {
                const __half* base = Bb + (wn + j * 8 + grp) * GSH + ko + 2 * tig;
                bf[j][0] = *(const unsigned*)(base);
                bf[j][1] = *(const unsigned*)(base + 8);
            }
#pragma unroll
            for (int i = 0; i < 4; i++)
#pragma unroll
                for (int j = 0; j < 4; j++)
                    mma_f16(acc[i][j], af[i], bf[j]);
        }
        __syncthreads();
        buf++; if (buf >= NSTG) buf -= NSTG;
    }

#pragma unroll
    for (int i = 0; i < 4; i++)
#pragma unroll
        for (int j = 0; j < 4; j++) {
            int r   = bm + wm + i * 16 + grp;
            int col = bn + wn + j * 8 + tig * 2;
            *(float2*)(C + (size_t)r * N + col) =
                make_float2(acc[i][j][0], acc[i][j][1]);
            *(float2*)(C + (size_t)(r + 8) * N + col) =
                make_float2(acc[i][j][2], acc[i][j][3]);
        }
}

// ---------------------------------------------------------------------------
// RoPE from fused qkv (fp32) -> half q (pre-scaled) and half k.
// ---------------------------------------------------------------------------
__global__ void rope_h_kernel(const float* __restrict__ qkv,
                              const float* __restrict__ fc, const float* __restrict__ fs,
                              __half* __restrict__ qh, __half* __restrict__ kh) {
    const int PAIRS = HD / 2;
    const float scale = 0.08838834764831845f;   // 1/sqrt(128)
    int idx = blockIdx.x * blockDim.x + threadIdx.x;
    const int TOT = SEQ * (NH + NKV) * PAIRS;
    if (idx >= TOT) return;
    int p = idx % PAIRS;
    int h = (idx / PAIRS) % (NH + NKV);
    int s = idx / (PAIRS * (NH + NKV));
    float c  = fc[s * PAIRS + p];
    float sn = fs[s * PAIRS + p];
    if (h < NH) {
        const float* src = qkv + (size_t)s * NQKV + h * HD + 2 * p;
        float2 ri = *(const float2*)src;
        float ox = (ri.x * c - ri.y * sn) * scale;
        float oy = (ri.x * sn + ri.y * c) * scale;
        *(__half2*)(qh + (size_t)s * DIM + h * HD + 2 * p) = __floats2half2_rn(ox, oy);
    } else {
        const float* src = qkv + (size_t)s * NQKV + DIM + (h - NH) * HD + 2 * p;
        float2 ri = *(const float2*)src;
        float ox = ri.x * c - ri.y * sn;
        float oy = ri.x * sn + ri.y * c;
        *(__half2*)(kh + (size_t)s * KVDIM + (h - NH) * HD + 2 * p) = __floats2half2_rn(ox, oy);
    }
}

// V transpose: qkv[seq][5120 + d] fp32 -> vt[d][seq] fp16
__global__ void transpose_v_kernel(const float* __restrict__ qkv, __half* __restrict__ vt) {
    __shared__ float t[32][33];
    int s0 = blockIdx.x * 32;
    int d0 = blockIdx.y * 32;
    int x = threadIdx.x, y = threadIdx.y;   // 32 x 8
#pragma unroll
    for (int j = 0; j < 32; j += 8)
        t[y + j][x] = qkv[(size_t)(s0 + y + j) * NQKV + DIM + KVDIM + d0 + x];
    __syncthreads();
#pragma unroll
    for (int j = 0; j < 32; j += 8)
        vt[(size_t)(d0 + y + j) * SEQ + s0 + x] = __float2half(t[x][y + j]);
}

// ---------------------------------------------------------------------------
// FP16 flash attention (causal, GQA). Occupancy 2; CTA order reversed so the
// heaviest (largest qbase) blocks launch first.
// Block = 128 q-rows x 1 head, 256 thr = 8 warps, warp owns 16 q-rows.
// ---------------------------------------------------------------------------
#define BQ   128
#define BK   64
#define FSH  136   // Qs/Ks row stride (halves)
#define VSH  72    // Vst/Ps row stride (halves)
#define FLASH_SMEM ((BQ * FSH + BK * FSH + HD * VSH + BQ * VSH) * 2)

__global__ __launch_bounds__(256, 2)
void flash_f16_kernel(const __half* __restrict__ Qh, const __half* __restrict__ Kh,
                      const __half* __restrict__ VT, __half* __restrict__ Y) {
    extern __shared__ __half fsm[];
    __half* Qs  = fsm;                    // 128 x FSH
    __half* Ks  = Qs + BQ * FSH;          // 64 x FSH
    __half* Vst = Ks + BK * FSH;          // 128(d) x VSH
    __half* Ps  = Vst + HD * VSH;         // 128 x VSH

    const int tid  = threadIdx.x;
    const int lane = tid & 31;
    const int w    = tid >> 5;
    const int grp  = lane >> 2;
    const int tig  = lane & 3;
    const int h    = blockIdx.y;
    const int kh   = h >> 2;
    const int qbase = (gridDim.x - 1 - blockIdx.x) * BQ;   // heavy blocks first
    const int m0   = w * 16;

    // Load Q tile (half, pre-scaled): 128 x 128 halves, 8 uint4 per thread
#pragma unroll
    for (int i = 0; i < 8; i++) {
        int id  = tid + i * 256;
        int row = id >> 4;
        int c8  = (id & 15) * 8;
        *(uint4*)(Qs + row * FSH + c8) =
            *(const uint4*)(Qh + (size_t)(qbase + row) * DIM + h * HD + c8);
    }

    float m0s = -1e30f, m1s = -1e30f, l0 = 0.0f, l1 = 0.0f;
    float o[16][4];
#pragma unroll
    for (int nt = 0; nt < 16; nt++)
#pragma unroll
        for (int t = 0; t < 4; t++) o[nt][t] = 0.0f;

    const int rowg0 = qbase + m0 + grp;
    const int rowg1 = rowg0 + 8;
    const int ntiles = (qbase + BQ) / BK;

    for (int kt = 0; kt < ntiles; kt++) {
        const int kbase = kt * BK;
        __syncthreads();

        // K tile: 64 x 128 halves (4 uint4/thread)
#pragma unroll
        for (int i = 0; i < 4; i++) {
            int id  = tid + i * 256;
            int row = id >> 4;
            int c8  = (id & 15) * 8;
            *(uint4*)(Ks + row * FSH + c8) =
                *(const uint4*)(Kh + (size_t)(kbase + row) * KVDIM + kh * HD + c8);
        }
        // V tile (transposed): 128 d-rows x 64 halves (4 uint4/thread)
#pragma unroll
        for (int i = 0; i < 4; i++) {
            int id  = tid + i * 256;
            int row = id >> 3;
            int c8  = (id & 7) * 8;
            *(uint4*)(Vst + row * VSH + c8) =
                *(const uint4*)(VT + (size_t)(kh * HD + row) * SEQ + kbase + c8);
        }
        __syncthreads();

        // S = Q K^T : 8 k16 steps, 8 n-tiles (scalar LDS fragments)
        float sacc[8][4];
#pragma unroll
        for (int nt = 0; nt < 8; nt++)
#pragma unroll
            for (int t = 0; t < 4; t++) sacc[nt][t] = 0.0f;

#pragma unroll
        for (int k16 = 0; k16 < 8; k16++) {
            const int ko = k16 * 16;
            unsigned a[4];
            const __half* ab = Qs + (m0 + grp) * FSH + ko + 2 * tig;
            a[0] = *(const unsigned*)(ab);
            a[1] = *(const unsigned*)(ab + 8 * FSH);
            a[2] = *(const unsigned*)(ab + 8);
            a[3] = *(const unsigned*)(ab + 8 * FSH + 8);
#pragma unroll
            for (int nt = 0; nt < 8; nt++) {
                unsigned b[2];
                const __half* bb = Ks + (nt * 8 + grp) * FSH + ko + 2 * tig;
                b[0] = *(const unsigned*)(bb);
                b[1] = *(const unsigned*)(bb + 8);
                mma_f16(sacc[nt], a, b);
            }
        }

        // Causal mask + online softmax (fp32)
        float rmax0 = -1e30f, rmax1 = -1e30f;
#pragma unroll
        for (int nt = 0; nt < 8; nt++) {
            int c0 = kbase + nt * 8 + 2 * tig;
            int c1 = c0 + 1;
            if (c0 > rowg0) sacc[nt][0] = -1e30f;
            if (c1 > rowg0) sacc[nt][1] = -1e30f;
            if (c0 > rowg1) sacc[nt][2] = -1e30f;
            if (c1 > rowg1) sacc[nt][3] = -1e30f;
            rmax0 = fmaxf(rmax0, fmaxf(sacc[nt][0], sacc[nt][1]));
            rmax1 = fmaxf(rmax1, fmaxf(sacc[nt][2], sacc[nt][3]));
        }
#pragma unroll
        for (int off = 1; off <= 2; off <<= 1) {
            rmax0 = fmaxf(rmax0, __shfl_xor_sync(0xFFFFFFFFu, rmax0, off));
            rmax1 = fmaxf(rmax1, __shfl_xor_sync(0xFFFFFFFFu, rmax1, off));
        }

        float mn0 = fmaxf(m0s, rmax0);
        float mn1 = fmaxf(m1s, rmax1);
        float alpha0 = __expf(m0s - mn0);
        float alpha1 = __expf(m1s - mn1);
        m0s = mn0; m1s = mn1;

        float psum0 = 0.0f, psum1 = 0.0f;
        __half* prow0 = Ps + (m0 + grp) * VSH;
        __half* prow1 = prow0 + 8 * VSH;
#pragma unroll
        for (int nt = 0; nt < 8; nt++) {
            float p0 = __expf(sacc[nt][0] - mn0);
            float p1 = __expf(sacc[nt][1] - mn0);
            float p2 = __expf(sacc[nt][2] - mn1);
            float p3 = __expf(sacc[nt][3] - mn1);
            psum0 += p0 + p1;
            psum1 += p2 + p3;
            *(unsigned*)(prow0 + nt * 8 + 2 * tig) = h2u(__floats2half2_rn(p0, p1));
            *(unsigned*)(prow1 + nt * 8 + 2 * tig) = h2u(__floats2half2_rn(p2, p3));
        }
#pragma unroll
        for (int off = 1; off <= 2; off <<= 1) {
            psum0 += __shfl_xor_sync(0xFFFFFFFFu, psum0, off);
            psum1 += __shfl_xor_sync(0xFFFFFFFFu, psum1, off);
        }
        l0 = l0 * alpha0 + psum0;
        l1 = l1 * alpha1 + psum1;

#pragma unroll
        for (int nt = 0; nt < 16; nt++) {
            o[nt][0] *= alpha0; o[nt][1] *= alpha0;
            o[nt][2] *= alpha1; o[nt][3] *= alpha1;
        }
        __syncwarp();

        // O += P V : 4 k16 steps over BK=64, 16 d-tiles (scalar LDS fragments)
#pragma unroll
        for (int k16 = 0; k16 < 4; k16++) {
            const int ko = k16 * 16;
            unsigned a[4];
            const __half* ab = Ps + (m0 + grp) * VSH + ko + 2 * tig;
            a[0] = *(const unsigned*)(ab);
            a[1] = *(const unsigned*)(ab + 8 * VSH);
            a[2] = *(const unsigned*)(ab + 8);
            a[3] = *(const unsigned*)(ab + 8 * VSH + 8);
#pragma unroll
            for (int nt = 0; nt < 16; nt++) {
                unsigned b[2];
                const __half* bb = Vst + (nt * 8 + grp) * VSH + ko + 2 * tig;
                b[0] = *(const unsigned*)(bb);
                b[1] = *(const unsigned*)(bb + 8);
                mma_f16(o[nt], a, b);
            }
        }
    }

    // Epilogue: normalize, write y as half for WO GEMM
    float inv0 = 1.0f / l0;
    float inv1 = 1.0f / l1;
    __half* y0 = Y + (size_t)rowg0 * DIM + h * HD;
    __half* y1 = Y + (size_t)rowg1 * DIM + h * HD;
#pragma unroll
    for (int nt = 0; nt < 16; nt++) {
        *(unsigned*)(y0 + nt * 8 + 2 * tig) =
            h2u(__floats2half2_rn(o[nt][0] * inv0, o[nt][1] * inv0));
        *(unsigned*)(y1 + nt * 8 + 2 * tig) =
            h2u(__floats2half2_rn(o[nt][2] * inv1, o[nt][3] * inv1));
    }
}

// ---------------------------------------------------------------------------
// Launch
// ---------------------------------------------------------------------------
extern "C" void kernel_launch(void* const* d_in, const int* in_sizes, int n_in,
                              void* d_out, int out_size) {
    const float* x  = (const float*)d_in[0];
    const float* wq = (const float*)d_in[1];
    const float* wk = (const float*)d_in[2];
    const float* wv = (const float*)d_in[3];
    const float* wo = (const float*)d_in[4];
    const float* fc = (const float*)d_in[5];
    const float* fs = (const float*)d_in[6];
    float* out = (float*)d_out;

    float* qkv;
    __half *qh, *kh2, *vth, *yh, *xh, *wqkvh, *woh;
    cudaGetSymbolAddress((void**)&qkv,   g_qkv);
    cudaGetSymbolAddress((void**)&qh,    g_qh);
    cudaGetSymbolAddress((void**)&kh2,   g_kh);
    cudaGetSymbolAddress((void**)&vth,   g_vth);
    cudaGetSymbolAddress((void**)&yh,    g_yh);
    cudaGetSymbolAddress((void**)&xh,    g_xh);
    cudaGetSymbolAddress((void**)&wqkvh, g_wqkvh);
    cudaGetSymbolAddress((void**)&woh,   g_woh);

    cudaFuncSetAttribute(gemm_f16_kernel, cudaFuncAttributeMaxDynamicSharedMemorySize,
                         GEMM_SMEM);
    cudaFuncSetAttribute(flash_f16_kernel, cudaFuncAttributeMaxDynamicSharedMemorySize,
                         FLASH_SMEM);

    // fp32 -> fp16 prepass (wq/wk/wv fused into one weight buffer)
    {
        int n4;
        n4 = SEQ * DIM / 4;
        cvt_h_kernel<<<(n4 + 255) / 256, 256>>>(x, xh, n4);
        n4 = DIM * DIM / 4;
        cvt_h_kernel<<<(n4 + 255) / 256, 256>>>(wq, wqkvh, n4);
        n4 = KVDIM * DIM / 4;
        cvt_h_kernel<<<(n4 + 255) / 256, 256>>>(wk, wqkvh + (size_t)DIM * DIM, n4);
        cvt_h_kernel<<<(n4 + 255) / 256, 256>>>(wv, wqkvh + (size_t)(DIM + KVDIM) * DIM, n4);
        n4 = DIM * DIM / 4;
        cvt_h_kernel<<<(n4 + 255) / 256, 256>>>(wo, woh, n4);
    }

    // Fused QKV projection: [2048, 6144] = x @ [wq;wk;wv]^T
    gemm_f16_kernel<<<dim3(NQKV / 128, SEQ / 128), 256, GEMM_SMEM>>>(
        xh, wqkvh, qkv, SEQ, NQKV, DIM);

    // RoPE -> half q (scaled) / half k
    int tot = SEQ * (NH + NKV) * (HD / 2);
    rope_h_kernel<<<(tot + 255) / 256, 256>>>(qkv, fc, fs, qh, kh2);

    // V transpose (fp32 slice of qkv -> half, d-major)
    transpose_v_kernel<<<dim3(SEQ / 32, KVDIM / 32), dim3(32, 8)>>>(qkv, vth);

    // Flash attention
    flash_f16_kernel<<<dim3(SEQ / BQ, NH), 256, FLASH_SMEM>>>(qh, kh2, vth, yh);

    // Output projection
    gemm_f16_kernel<<<dim3(DIM / 128, SEQ / 128), 256, GEMM_SMEM>>>(
        yh, woh, out, SEQ, DIM, DIM);
}

// round 16
// speedup vs baseline: 1.0166x; 1.0166x over previous
#include <cuda_runtime.h>
#include <cuda_fp16.h>
#include <math.h>
#include <stdint.h>

#define SEQ   2048
#define DIM   4096
#define NH    32
#define NKV   8
#define HD    128
#define KVDIM (NKV * HD)   // 1024
#define NQKV  (DIM + 2 * KVDIM)   // 6144

// Scratch (device globals: allocation-free rule)
__device__ float  g_qkv[SEQ * NQKV];          // fused QKV projection output (fp32)
__device__ __half g_qh[SEQ * DIM];            // roped, scaled by 1/sqrt(hd)*log2e (half)
__device__ __half g_kh[SEQ * KVDIM];          // roped K (half)
__device__ __half g_vth[KVDIM * SEQ];         // V transposed [kvdim][seq] (half)
__device__ __half g_yh[SEQ * DIM];            // attention output (half)
__device__ __half g_xh[SEQ * DIM];
__device__ __half g_wqkvh[NQKV * DIM];        // fused [wq; wk; wv] (half)
__device__ __half g_woh[DIM * DIM];

// ---------------------------------------------------------------------------
// Helpers
// ---------------------------------------------------------------------------
__device__ __forceinline__ unsigned h2u(__half2 h) { return *(unsigned*)&h; }

__device__ __forceinline__ void cp16(void* smem_dst, const void* gsrc) {
    unsigned d = (unsigned)__cvta_generic_to_shared(smem_dst);
    asm volatile("cp.async.cg.shared.global [%0], [%1], 16;" :: "r"(d), "l"(gsrc));
}
__device__ __forceinline__ void mma_f16(float c[4], const unsigned a[4], const unsigned b[2]) {
    asm volatile(
        "mma.sync.aligned.m16n8k16.row.col.f32.f16.f16.f32 "
        "{%0,%1,%2,%3}, {%4,%5,%6,%7}, {%8,%9}, {%0,%1,%2,%3};"
        : "+f"(c[0]), "+f"(c[1]), "+f"(c[2]), "+f"(c[3])
        : "r"(a[0]), "r"(a[1]), "r"(a[2]), "r"(a[3]), "r"(b[0]), "r"(b[1]));
}

// ---------------------------------------------------------------------------
// Single fused fp32 -> fp16 conversion prepass for all five operand tensors.
// ---------------------------------------------------------------------------
#define NX4   (SEQ * DIM / 4)
#define NWQ4  (DIM * DIM / 4)
#define NWK4  (KVDIM * DIM / 4)
#define NWV4  (KVDIM * DIM / 4)
#define NWO4  (DIM * DIM / 4)
#define NTOT4 (NX4 + NWQ4 + NWK4 + NWV4 + NWO4)

__global__ void cvt_all_kernel(const float* __restrict__ x,  const float* __restrict__ wq,
                               const float* __restrict__ wk, const float* __restrict__ wv,
                               const float* __restrict__ wo,
                               __half* __restrict__ xh, __half* __restrict__ wqkvh,
                               __half* __restrict__ woh) {
    int i = blockIdx.x * blockDim.x + threadIdx.x;
    if (i >= NTOT4) return;
    const float* src;
    __half* dst;
    int j = i;
    if (j < NX4)                       { src = x;  dst = xh; }
    else if ((j -= NX4) < NWQ4)        { src = wq; dst = wqkvh; }
    else if ((j -= NWQ4) < NWK4)       { src = wk; dst = wqkvh + (size_t)DIM * DIM; }
    else if ((j -= NWK4) < NWV4)       { src = wv; dst = wqkvh + (size_t)(DIM + KVDIM) * DIM; }
    else                               { j -= NWV4; src = wo; dst = woh; }
    float4 v = ((const float4*)src)[j];
    ((uint2*)dst)[j] = make_uint2(h2u(__floats2half2_rn(v.x, v.y)),
                                  h2u(__floats2half2_rn(v.z, v.w)));
}

// ---------------------------------------------------------------------------
// FP16 GEMM (NT): C[M,N] = A[M,K] * B[N,K]^T, fp16 in / fp32 out.
// 128x128 tile, BK=32, 256 thr, 8 warps x (64x32), cp.async 3-stage pipeline.
// ---------------------------------------------------------------------------
#define GSH 56   // smem row stride in halves (112B, conflict-free, 16B-aligned)
#define NSTG 3
#define GEMM_SMEM (2 * NSTG * 128 * GSH * 2)   // 86016 B

__global__ __launch_bounds__(256, 2)
void gemm_f16_kernel(const __half* __restrict__ A, const __half* __restrict__ B,
                     float* __restrict__ C, int M, int N, int K) {
    extern __shared__ __half hsm[];
    __half* As = hsm;                      // [NSTG][128*GSH]
    __half* Bs = hsm + NSTG * 128 * GSH;

    const int tid  = threadIdx.x;
    const int lane = tid & 31;
    const int wid  = tid >> 5;
    const int grp  = lane >> 2;
    const int tig  = lane & 3;

    const int bm = blockIdx.y * 128;
    const int bn = blockIdx.x * 128;
    const int wm = (wid & 1) * 64;
    const int wn = (wid >> 1) * 32;

    float acc[4][4][4];
#pragma unroll
    for (int i = 0; i < 4; i++)
#pragma unroll
        for (int j = 0; j < 4; j++)
#pragma unroll
            for (int t = 0; t < 4; t++) acc[i][j][t] = 0.0f;

    const int nk = K / 32;

    auto load_stage = [&](int t, int buf) {
        const int koff = t * 32;
        __half* Ad = As + buf * 128 * GSH;
        __half* Bd = Bs + buf * 128 * GSH;
#pragma unroll
        for (int u = 0; u < 2; u++) {
            int id  = tid + u * 256;
            int row = id >> 2;
            int o8  = (id & 3) * 8;
            cp16(Ad + row * GSH + o8, A + (size_t)(bm + row) * K + koff + o8);
            cp16(Bd + row * GSH + o8, B + (size_t)(bn + row) * K + koff + o8);
        }
    };

    // prologue: stages 0,1
    load_stage(0, 0);
    asm volatile("cp.async.commit_group;");
    load_stage(1, 1);
    asm volatile("cp.async.commit_group;");

    int buf = 0;   // buffer of chunk t
    for (int t = 0; t < nk; t++) {
        if (t + 2 < nk) {
            int nb = buf + 2; if (nb >= NSTG) nb -= NSTG;
            load_stage(t + 2, nb);
            asm volatile("cp.async.commit_group;");
        }
        int rem = nk - 1 - t;
        if (rem >= 2)      asm volatile("cp.async.wait_group 2;");
        else if (rem == 1) asm volatile("cp.async.wait_group 1;");
        else               asm volatile("cp.async.wait_group 0;");
        __syncthreads();

        const __half* Ab = As + buf * 128 * GSH;
        const __half* Bb = Bs + buf * 128 * GSH;
#pragma unroll
        for (int kk = 0; kk < 2; kk++) {      // two k16 steps per BK=32
            const int ko = kk * 16;
            unsigned af[4][4], bf[4][2];
#pragma unroll
            for (int i = 0; i < 4; i++) {
                const __half* base = Ab + (wm + i * 16 + grp) * GSH + ko + 2 * tig;
                af[i][0] = *(const unsigned*)(base);
                af[i][1] = *(const unsigned*)(base + 8 * GSH);
                af[i][2] = *(const unsigned*)(base + 8);
                af[i][3] = *(const unsigned*)(base + 8 * GSH + 8);
            }
#pragma unroll
            for (int j = 0; j < 4; j++) {
                const __half* base = Bb + (wn + j * 8 + grp) * GSH + ko + 2 * tig;
                bf[j][0] = *(const unsigned*)(base);
                bf[j][1] = *(const unsigned*)(base + 8);
            }
#pragma unroll
            for (int i = 0; i < 4; i++)
#pragma unroll
                for (int j = 0; j < 4; j++)
                    mma_f16(acc[i][j], af[i], bf[j]);
        }
        __syncthreads();
        buf++; if (buf >= NSTG) buf -= NSTG;
    }

#pragma unroll
    for (int i = 0; i < 4; i++)
#pragma unroll
        for (int j = 0; j < 4; j++) {
            int r   = bm + wm + i * 16 + grp;
            int col = bn + wn + j * 8 + tig * 2;
            *(float2*)(C + (size_t)r * N + col) =
                make_float2(acc[i][j][0], acc[i][j][1]);
            *(float2*)(C + (size_t)(r + 8) * N + col) =
                make_float2(acc[i][j][2], acc[i][j][3]);
        }
}

// ---------------------------------------------------------------------------
// RoPE from fused qkv (fp32) -> half q (pre-scaled by 1/sqrt(hd)*log2e for
// exp2-domain softmax) and half k.
// ---------------------------------------------------------------------------
__global__ void rope_h_kernel(const float* __restrict__ qkv,
                              const float* __restrict__ fc, const float* __restrict__ fs,
                              __half* __restrict__ qh, __half* __restrict__ kh) {
    const int PAIRS = HD / 2;
    const float scale = 0.08838834764831845f * 1.4426950408889634f;  // /sqrt(128) * log2e
    int idx = blockIdx.x * blockDim.x + threadIdx.x;
    const int TOT = SEQ * (NH + NKV) * PAIRS;
    if (idx >= TOT) return;
    int p = idx % PAIRS;
    int h = (idx / PAIRS) % (NH + NKV);
    int s = idx / (PAIRS * (NH + NKV));
    float c  = fc[s * PAIRS + p];
    float sn = fs[s * PAIRS + p];
    if (h < NH) {
        const float* src = qkv + (size_t)s * NQKV + h * HD + 2 * p;
        float2 ri = *(const float2*)src;
        float ox = (ri.x * c - ri.y * sn) * scale;
        float oy = (ri.x * sn + ri.y * c) * scale;
        *(__half2*)(qh + (size_t)s * DIM + h * HD + 2 * p) = __floats2half2_rn(ox, oy);
    } else {
        const float* src = qkv + (size_t)s * NQKV + DIM + (h - NH) * HD + 2 * p;
        float2 ri = *(const float2*)src;
        float ox = ri.x * c - ri.y * sn;
        float oy = ri.x * sn + ri.y * c;
        *(__half2*)(kh + (size_t)s * KVDIM + (h - NH) * HD + 2 * p) = __floats2half2_rn(ox, oy);
    }
}

// V transpose: qkv[seq][5120 + d] fp32 -> vt[d][seq] fp16
__global__ void transpose_v_kernel(const float* __restrict__ qkv, __half* __restrict__ vt) {
    __shared__ float t[32][33];
    int s0 = blockIdx.x * 32;
    int d0 = blockIdx.y * 32;
    int x = threadIdx.x, y = threadIdx.y;   // 32 x 8
#pragma unroll
    for (int j = 0; j < 32; j += 8)
        t[y + j][x] = qkv[(size_t)(s0 + y + j) * NQKV + DIM + KVDIM + d0 + x];
    __syncthreads();
#pragma unroll
    for (int j = 0; j < 32; j += 8)
        vt[(size_t)(d0 + y + j) * SEQ + s0 + x] = __float2half(t[x][y + j]);
}

// ---------------------------------------------------------------------------
// FP16 flash attention (causal, GQA). exp2-domain softmax (Q pre-scaled by
// log2e). Occupancy 2; CTA order reversed (heavy blocks first).
// Block = 128 q-rows x 1 head, 256 thr = 8 warps, warp owns 16 q-rows.
// ---------------------------------------------------------------------------
#define BQ   128
#define BK   64
#define FSH  136   // Qs/Ks row stride (halves)
#define VSH  72    // Vst/Ps row stride (halves)
#define FLASH_SMEM ((BQ * FSH + BK * FSH + HD * VSH + BQ * VSH) * 2)

__global__ __launch_bounds__(256, 2)
void flash_f16_kernel(const __half* __restrict__ Qh, const __half* __restrict__ Kh,
                      const __half* __restrict__ VT, __half* __restrict__ Y) {
    extern __shared__ __half fsm[];
    __half* Qs  = fsm;                    // 128 x FSH
    __half* Ks  = Qs + BQ * FSH;          // 64 x FSH
    __half* Vst = Ks + BK * FSH;          // 128(d) x VSH
    __half* Ps  = Vst + HD * VSH;         // 128 x VSH

    const int tid  = threadIdx.x;
    const int lane = tid & 31;
    const int w    = tid >> 5;
    const int grp  = lane >> 2;
    const int tig  = lane & 3;
    const int h    = blockIdx.y;
    const int kh   = h >> 2;
    const int qbase = (gridDim.x - 1 - blockIdx.x) * BQ;   // heavy blocks first
    const int m0   = w * 16;

    // Load Q tile (half, pre-scaled): 128 x 128 halves, 8 uint4 per thread
#pragma unroll
    for (int i = 0; i < 8; i++) {
        int id  = tid + i * 256;
        int row = id >> 4;
        int c8  = (id & 15) * 8;
        *(uint4*)(Qs + row * FSH + c8) =
            *(const uint4*)(Qh + (size_t)(qbase + row) * DIM + h * HD + c8);
    }

    float m0s = -1e30f, m1s = -1e30f, l0 = 0.0f, l1 = 0.0f;
    float o[16][4];
#pragma unroll
    for (int nt = 0; nt < 16; nt++)
#pragma unroll
        for (int t = 0; t < 4; t++) o[nt][t] = 0.0f;

    const int rowg0 = qbase + m0 + grp;
    const int rowg1 = rowg0 + 8;
    const int ntiles = (qbase + BQ) / BK;

    for (int kt = 0; kt < ntiles; kt++) {
        const int kbase = kt * BK;
        __syncthreads();

        // K tile: 64 x 128 halves (4 uint4/thread)
#pragma unroll
        for (int i = 0; i < 4; i++) {
            int id  = tid + i * 256;
            int row = id >> 4;
            int c8  = (id & 15) * 8;
            *(uint4*)(Ks + row * FSH + c8) =
                *(const uint4*)(Kh + (size_t)(kbase + row) * KVDIM + kh * HD + c8);
        }
        // V tile (transposed): 128 d-rows x 64 halves (4 uint4/thread)
#pragma unroll
        for (int i = 0; i < 4; i++) {
            int id  = tid + i * 256;
            int row = id >> 3;
            int c8  = (id & 7) * 8;
            *(uint4*)(Vst + row * VSH + c8) =
                *(const uint4*)(VT + (size_t)(kh * HD + row) * SEQ + kbase + c8);
        }
        __syncthreads();

        // S = Q K^T (in log2 domain): 8 k16 steps, 8 n-tiles
        float sacc[8][4];
#pragma unroll
        for (int nt = 0; nt < 8; nt++)
#pragma unroll
            for (int t = 0; t < 4; t++) sacc[nt][t] = 0.0f;

#pragma unroll
        for (int k16 = 0; k16 < 8; k16++) {
            const int ko = k16 * 16;
            unsigned a[4];
            const __half* ab = Qs + (m0 + grp) * FSH + ko + 2 * tig;
            a[0] = *(const unsigned*)(ab);
            a[1] = *(const unsigned*)(ab + 8 * FSH);
            a[2] = *(const unsigned*)(ab + 8);
            a[3] = *(const unsigned*)(ab + 8 * FSH + 8);
#pragma unroll
            for (int nt = 0; nt < 8; nt++) {
                unsigned b[2];
                const __half* bb = Ks + (nt * 8 + grp) * FSH + ko + 2 * tig;
                b[0] = *(const unsigned*)(bb);
                b[1] = *(const unsigned*)(bb + 8);
                mma_f16(sacc[nt], a, b);
            }
        }

        // Causal mask + online softmax (exp2 domain, fp32 state)
        float rmax0 = -1e30f, rmax1 = -1e30f;
#pragma unroll
        for (int nt = 0; nt < 8; nt++) {
            int c0 = kbase + nt * 8 + 2 * tig;
            int c1 = c0 + 1;
            if (c0 > rowg0) sacc[nt][0] = -1e30f;
            if (c1 > rowg0) sacc[nt][1] = -1e30f;
            if (c0 > rowg1) sacc[nt][2] = -1e30f;
            if (c1 > rowg1) sacc[nt][3] = -1e30f;
            rmax0 = fmaxf(rmax0, fmaxf(sacc[nt][0], sacc[nt][1]));
            rmax1 = fmaxf(rmax1, fmaxf(sacc[nt][2], sacc[nt][3]));
        }
#pragma unroll
        for (int off = 1; off <= 2; off <<= 1) {
            rmax0 = fmaxf(rmax0, __shfl_xor_sync(0xFFFFFFFFu, rmax0, off));
            rmax1 = fmaxf(rmax1, __shfl_xor_sync(0xFFFFFFFFu, rmax1, off));
        }

        float mn0 = fmaxf(m0s, rmax0);
        float mn1 = fmaxf(m1s, rmax1);
        float alpha0 = exp2f(m0s - mn0);
        float alpha1 = exp2f(m1s - mn1);
        m0s = mn0; m1s = mn1;

        float psum0 = 0.0f, psum1 = 0.0f;
        __half* prow0 = Ps + (m0 + grp) * VSH;
        __half* prow1 = prow0 + 8 * VSH;
#pragma unroll
        for (int nt = 0; nt < 8; nt++) {
            float p0 = exp2f(sacc[nt][0] - mn0);
            float p1 = exp2f(sacc[nt][1] - mn0);
            float p2 = exp2f(sacc[nt][2] - mn1);
            float p3 = exp2f(sacc[nt][3] - mn1);
            psum0 += p0 + p1;
            psum1 += p2 + p3;
            *(unsigned*)(prow0 + nt * 8 + 2 * tig) = h2u(__floats2half2_rn(p0, p1));
            *(unsigned*)(prow1 + nt * 8 + 2 * tig) = h2u(__floats2half2_rn(p2, p3));
        }
#pragma unroll
        for (int off = 1; off <= 2; off <<= 1) {
            psum0 += __shfl_xor_sync(0xFFFFFFFFu, psum0, off);
            psum1 += __shfl_xor_sync(0xFFFFFFFFu, psum1, off);
        }
        l0 = l0 * alpha0 + psum0;
        l1 = l1 * alpha1 + psum1;

#pragma unroll
        for (int nt = 0; nt < 16; nt++) {
            o[nt][0] *= alpha0; o[nt][1] *= alpha0;
            o[nt][2] *= alpha1; o[nt][3] *= alpha1;
        }
        __syncwarp();

        // O += P V : 4 k16 steps over BK=64, 16 d-tiles
#pragma unroll
        for (int k16 = 0; k16 < 4; k16++) {
            const int ko = k16 * 16;
            unsigned a[4];
            const __half* ab = Ps + (m0 + grp) * VSH + ko + 2 * tig;
            a[0] = *(const unsigned*)(ab);
            a[1] = *(const unsigned*)(ab + 8 * VSH);
            a[2] = *(const unsigned*)(ab + 8);
            a[3] = *(const unsigned*)(ab + 8 * VSH + 8);
#pragma unroll
            for (int nt = 0; nt < 16; nt++) {
                unsigned b[2];
                const __half* bb = Vst + (nt * 8 + grp) * VSH + ko + 2 * tig;
                b[0] = *(const unsigned*)(bb);
                b[1] = *(const unsigned*)(bb + 8);
                mma_f16(o[nt], a, b);
            }
        }
    }

    // Epilogue: normalize, write y as half for WO GEMM
    float inv0 = 1.0f / l0;
    float inv1 = 1.0f / l1;
    __half* y0 = Y + (size_t)rowg0 * DIM + h * HD;
    __half* y1 = Y + (size_t)rowg1 * DIM + h * HD;
#pragma unroll
    for (int nt = 0; nt < 16; nt++) {
        *(unsigned*)(y0 + nt * 8 + 2 * tig) =
            h2u(__floats2half2_rn(o[nt][0] * inv0, o[nt][1] * inv0));
        *(unsigned*)(y1 + nt * 8 + 2 * tig) =
            h2u(__floats2half2_rn(o[nt][2] * inv1, o[nt][3] * inv1));
    }
}

// ---------------------------------------------------------------------------
// Launch
// ---------------------------------------------------------------------------
extern "C" void kernel_launch(void* const* d_in, const int* in_sizes, int n_in,
                              void* d_out, int out_size) {
    const float* x  = (const float*)d_in[0];
    const float* wq = (const float*)d_in[1];
    const float* wk = (const float*)d_in[2];
    const float* wv = (const float*)d_in[3];
    const float* wo = (const float*)d_in[4];
    const float* fc = (const float*)d_in[5];
    const float* fs = (const float*)d_in[6];
    float* out = (float*)d_out;

    float* qkv;
    __half *qh, *kh2, *vth, *yh, *xh, *wqkvh, *woh;
    cudaGetSymbolAddress((void**)&qkv,   g_qkv);
    cudaGetSymbolAddress((void**)&qh,    g_qh);
    cudaGetSymbolAddress((void**)&kh2,   g_kh);
    cudaGetSymbolAddress((void**)&vth,   g_vth);
    cudaGetSymbolAddress((void**)&yh,    g_yh);
    cudaGetSymbolAddress((void**)&xh,    g_xh);
    cudaGetSymbolAddress((void**)&wqkvh, g_wqkvh);
    cudaGetSymbolAddress((void**)&woh,   g_woh);

    cudaFuncSetAttribute(gemm_f16_kernel, cudaFuncAttributeMaxDynamicSharedMemorySize,
                         GEMM_SMEM);
    cudaFuncSetAttribute(flash_f16_kernel, cudaFuncAttributeMaxDynamicSharedMemorySize,
                         FLASH_SMEM);

    // Single fused fp32 -> fp16 prepass (1 launch instead of 5)
    cvt_all_kernel<<<(NTOT4 + 255) / 256, 256>>>(x, wq, wk, wv, wo, xh, wqkvh, woh);

    // Fused QKV projection: [2048, 6144] = x @ [wq;wk;wv]^T
    gemm_f16_kernel<<<dim3(NQKV / 128, SEQ / 128), 256, GEMM_SMEM>>>(
        xh, wqkvh, qkv, SEQ, NQKV, DIM);

    // RoPE -> half q (scaled, log2e-domain) / half k
    int tot = SEQ * (NH + NKV) * (HD / 2);
    rope_h_kernel<<<(tot + 255) / 256, 256>>>(qkv, fc, fs, qh, kh2);

    // V transpose (fp32 slice of qkv -> half, d-major)
    transpose_v_kernel<<<dim3(SEQ / 32, KVDIM / 32), dim3(32, 8)>>>(qkv, vth);

    // Flash attention
    flash_f16_kernel<<<dim3(SEQ / BQ, NH), 256, FLASH_SMEM>>>(qh, kh2, vth, yh);

    // Output projection
    gemm_f16_kernel<<<dim3(DIM / 128, SEQ / 128), 256, GEMM_SMEM>>>(
        yh, woh, out, SEQ, DIM, DIM);
}